// round 5
// baseline (speedup 1.0000x reference)
#include <cuda_runtime.h>
#include <cuda_bf16.h>

// 8x8 DCT-II coefficients, 0.5*cos(pi*(2m+1)k/16) pre-folded (orthonormal).
#define K0 0.3535533905932738f   // 1/(2*sqrt(2))
#define K1 0.4903926402016152f
#define K2 0.4619397662556434f
#define K3 0.4157348061512726f
#define K5 0.2777851165098011f
#define K6 0.1913417161825449f
#define K7 0.0975451610080642f

// In-place 8-point DCT-II (orthonormal), butterfly (even/odd) form.
__device__ __forceinline__ void dct8(float* v) {
    float s0 = v[0] + v[7], s1 = v[1] + v[6], s2 = v[2] + v[5], s3 = v[3] + v[4];
    float d0 = v[0] - v[7], d1 = v[1] - v[6], d2 = v[2] - v[5], d3 = v[3] - v[4];
    float e0 = s0 + s3, e1 = s1 + s2;
    float o0 = s0 - s3, o1 = s1 - s2;
    v[0] = K0 * (e0 + e1);
    v[4] = K0 * (e0 - e1);
    v[2] = K2 * o0 + K6 * o1;
    v[6] = K6 * o0 - K2 * o1;
    v[1] = K1 * d0 + K3 * d1 + K5 * d2 + K7 * d3;
    v[3] = K3 * d0 - K7 * d1 - K1 * d2 - K5 * d3;
    v[5] = K5 * d0 - K1 * d1 + K7 * d2 + K3 * d3;
    v[7] = K7 * d0 - K5 * d1 + K3 * d2 - K1 * d3;
}

// Warp = 8x64 strip = two 8x32 tiles, each tile = 4 adjacent 8x8 blocks.
// Thread (j = lane>>2, b = lane&3): row j of block b in BOTH tiles (ILP-2).
// 4 front-batched LDG.128 per thread -> doubled MLP vs one-tile version.
__global__ void __launch_bounds__(256)
dct_quant_kernel(const float* __restrict__ x,
                 const float* __restrict__ q,
                 float* __restrict__ out,
                 int nwarps) {
    __shared__ float srq[8][64];           // per-warp 1/q (no CTA-wide barrier)
    __shared__ float tr[8][2][4][8][9];    // [warp][tile][block][col][row], pad 9

    int wid  = threadIdx.x >> 5;
    int lane = threadIdx.x & 31;

    // Per-warp q-table reciprocal init; visibility guaranteed by the
    // __syncwarp() below (before any cross-lane read).
    srq[wid][lane]      = 1.0f / q[lane];
    srq[wid][lane + 32] = 1.0f / q[lane + 32];

    int w = blockIdx.x * 8 + wid;
    if (w >= nwarps) return;               // whole warps exit together
    int j = lane >> 2;   // row within block (becomes horizontal-freq index)
    int b = lane & 3;    // block within tile

    // strips: 2048 planes x 16 block-rows x 2 strip-cols
    int img = w >> 5;
    int rem = w & 31;
    int br  = rem >> 1;
    int tp  = rem & 1;
    long tile = ((long)img << 14) + (br << 10) + (tp << 6);

    const float* baseA = x + tile + j * 128 + b * 8;
    const float* baseB = baseA + 32;

    // Front-batched: 4 independent LDG.128
    float4 a0 = *reinterpret_cast<const float4*>(baseA);
    float4 a1 = *reinterpret_cast<const float4*>(baseA + 4);
    float4 b0 = *reinterpret_cast<const float4*>(baseB);
    float4 b1 = *reinterpret_cast<const float4*>(baseB + 4);

    float rA[8], rB[8];
    rA[0] = a0.x; rA[1] = a0.y; rA[2] = a0.z; rA[3] = a0.w;
    rA[4] = a1.x; rA[5] = a1.y; rA[6] = a1.z; rA[7] = a1.w;
    rB[0] = b0.x; rB[1] = b0.y; rB[2] = b0.z; rB[3] = b0.w;
    rB[4] = b1.x; rB[5] = b1.y; rB[6] = b1.z; rB[7] = b1.w;

    // Row pass (two independent chains -> good ILP)
    dct8(rA);
    dct8(rB);

    // Transposed write: tr[wid][t][b][c][j]. Bank = (8b + 9c + j) mod 32:
    // all 32 lanes distinct for fixed c -> conflict-free.
    float* tsA = &tr[wid][0][b][0][0];
    float* tsB = &tr[wid][1][b][0][0];
    #pragma unroll
    for (int c = 0; c < 8; c++) { tsA[c * 9 + j] = rA[c]; tsB[c * 9 + j] = rB[c]; }

    __syncwarp();

    // Row-contiguous read of transposed data: bank (8b + 9j + i) mod 32,
    // all distinct for fixed i -> conflict-free.
    #pragma unroll
    for (int i = 0; i < 8; i++) { rA[i] = tsA[j * 9 + i]; rB[i] = tsB[j * 9 + i]; }

    // Column pass
    dct8(rA);
    dct8(rB);

    // Quantize + round-half-even + clip, store column-oriented.
    // For fixed v, each tile's warp-write is one contiguous 128B segment.
    const float* sq = srq[wid];
    float* oA = out + tile + b * 8 + j;
    float* oB = oA + 32;
    #pragma unroll
    for (int v = 0; v < 8; v++) {
        float s  = sq[v * 8 + j];
        float yA = fminf(fmaxf(rintf(rA[v] * s), -128.0f), 127.0f);
        float yB = fminf(fmaxf(rintf(rB[v] * s), -128.0f), 127.0f);
        oA[v * 128] = yA;
        oB[v * 128] = yB;
    }
}

extern "C" void kernel_launch(void* const* d_in, const int* in_sizes, int n_in,
                              void* d_out, int out_size) {
    const float* x = (const float*)d_in[0];
    const float* q = (const float*)d_in[1];
    float* out = (float*)d_out;

    int nelem  = in_sizes[0];         // 33554432
    int nwarps = nelem / 512;         // 65536 warps (8x64 strip each)
    int grid   = (nwarps + 7) / 8;    // 8192 CTAs of 256 threads

    dct_quant_kernel<<<grid, 256>>>(x, q, out, nwarps);
}

// round 6
// speedup vs baseline: 1.2824x; 1.2824x over previous
#include <cuda_runtime.h>
#include <cuda_bf16.h>

// 8x8 DCT-II coefficients, 0.5*cos(pi*(2m+1)k/16) pre-folded (orthonormal).
#define K0 0.3535533905932738f   // 1/(2*sqrt(2))
#define K1 0.4903926402016152f
#define K2 0.4619397662556434f
#define K3 0.4157348061512726f
#define K5 0.2777851165098011f
#define K6 0.1913417161825449f
#define K7 0.0975451610080642f

// In-place 8-point DCT-II (orthonormal), butterfly (even/odd) form.
__device__ __forceinline__ void dct8(float* v) {
    float s0 = v[0] + v[7], s1 = v[1] + v[6], s2 = v[2] + v[5], s3 = v[3] + v[4];
    float d0 = v[0] - v[7], d1 = v[1] - v[6], d2 = v[2] - v[5], d3 = v[3] - v[4];
    float e0 = s0 + s3, e1 = s1 + s2;
    float o0 = s0 - s3, o1 = s1 - s2;
    v[0] = K0 * (e0 + e1);
    v[4] = K0 * (e0 - e1);
    v[2] = K2 * o0 + K6 * o1;
    v[6] = K6 * o0 - K2 * o1;
    v[1] = K1 * d0 + K3 * d1 + K5 * d2 + K7 * d3;
    v[3] = K3 * d0 - K7 * d1 - K1 * d2 - K5 * d3;
    v[5] = K5 * d0 - K1 * d1 + K7 * d2 + K3 * d3;
    v[7] = K7 * d0 - K5 * d1 + K3 * d2 - K1 * d3;
}

// Warp = 4 horizontally adjacent 8x8 blocks (an 8x32 tile, rows = 128B).
// Thread (j = lane>>2, b = lane&3): row j of block b. MLP_p1 = 2 (deliberate:
// deeper front-batching regressed via cross-CTA L1tex-queue contention).
// Transpose through padded per-warp SMEM (conflict-free both directions).
__global__ void __launch_bounds__(256)
dct_quant_kernel(const float* __restrict__ x,
                 const float* __restrict__ q,
                 float* __restrict__ out,
                 int nwarps) {
    __shared__ float srq[8][64];         // per-warp 1/q -> no CTA-entry barrier
    __shared__ float tr[8][4][8][9];     // [warp][block][col][row], pad 9

    int wid  = threadIdx.x >> 5;
    int lane = threadIdx.x & 31;

    int w = blockIdx.x * 8 + wid;
    if (w >= nwarps) return;             // whole warps exit together
    int j = lane >> 2;   // row within block (becomes horizontal-freq index)
    int b = lane & 3;    // block within tile

    // tiles: 2048 planes x 16 block-rows x 4 tile-cols
    int img = w >> 6;
    int br  = (w >> 2) & 15;
    int tc  = w & 3;
    long tile = ((long)img << 14) + (br << 10) + (tc << 5);

    const float* base = x + tile + j * 128 + b * 8;

    // Streaming loads (use-once data, evict-first)
    float4 lo = __ldcs(reinterpret_cast<const float4*>(base));
    float4 hi = __ldcs(reinterpret_cast<const float4*>(base + 4));

    // Per-warp q reciprocal init: independent of loads, covered by __syncwarp.
    srq[wid][lane]      = 1.0f / q[lane];
    srq[wid][lane + 32] = 1.0f / q[lane + 32];

    float r[8];
    r[0] = lo.x; r[1] = lo.y; r[2] = lo.z; r[3] = lo.w;
    r[4] = hi.x; r[5] = hi.y; r[6] = hi.z; r[7] = hi.w;

    // Row pass (along memory-contiguous dimension)
    dct8(r);

    // Transposed write: tr[wid][b][c][j] = r[c].
    // Banks (8b + 9c + j) mod 32: all 32 distinct for fixed c -> conflict-free.
    float* ts = &tr[wid][b][0][0];
    #pragma unroll
    for (int c = 0; c < 8; c++) ts[c * 9 + j] = r[c];

    __syncwarp();

    // Row-contiguous read of the transposed data: r[i] = R[i][j] (column j).
    // Banks (8b + 9j + i) mod 32: all 32 distinct for fixed i -> conflict-free.
    #pragma unroll
    for (int i = 0; i < 8; i++) r[i] = ts[j * 9 + i];

    // Column pass: register index v = vertical frequency, j = horizontal freq
    dct8(r);

    // Quantize + round-half-even + clip, store column-oriented (streaming).
    // For fixed v, warp writes tile + v*128 + {b*8+j over lanes}: one
    // contiguous, fully-coalesced 128B segment per STG.
    const float* sq = srq[wid];
    float* obase = out + tile + b * 8 + j;
    #pragma unroll
    for (int v = 0; v < 8; v++) {
        float y = rintf(r[v] * sq[v * 8 + j]);
        y = fminf(fmaxf(y, -128.0f), 127.0f);
        __stcs(obase + v * 128, y);
    }
}

extern "C" void kernel_launch(void* const* d_in, const int* in_sizes, int n_in,
                              void* d_out, int out_size) {
    const float* x = (const float*)d_in[0];
    const float* q = (const float*)d_in[1];
    float* out = (float*)d_out;

    int nelem  = in_sizes[0];         // 33554432
    int nwarps = nelem / 256;         // 131072 warps (4 blocks each)
    int grid   = (nwarps + 7) / 8;    // 16384 CTAs of 256 threads

    dct_quant_kernel<<<grid, 256>>>(x, q, out, nwarps);
}